// round 14
// baseline (speedup 1.0000x reference)
#include <cuda_runtime.h>
#include <cuda_fp16.h>
#include <math.h>
#include <stdint.h>

#define BB   512
#define TT   256
#define PP   61
#define HE   256
#define LATD 512
#define DECD 32
#define TBAR 16
#define NROWS (BB*TT)   // 131072
#define NBLK 128

// ---------------- scratch ----------------
__device__ float g_enc[(size_t)NROWS*512];          // (B*T, 2H)
__device__ float g_xp[(size_t)2*TT*1024*BB];        // [dir][pos][n][b]
__device__ __half g_h[2*2*BB*HE];                   // [dir][parity][b][j] fp16
__device__ float g_emb[(size_t)BB*TBAR*DECD];
__device__ uint32_t g_whh[270336];                  // [dir][nt][n 128][kp 132] fp16x2 hi (k-perm)
__device__ uint32_t g_whl[270336];                  // fp16x2 lo (k-perm)

__device__ unsigned g_cnt[16];
__device__ volatile unsigned g_sns[16];

typedef unsigned long long u64;

__device__ __forceinline__ float sigmoidf_(float v){ return 1.f/(1.f+__expf(-v)); }
__device__ __forceinline__ float tanh_ap(float v){
    float r; asm("tanh.approx.f32 %0, %1;" : "=f"(r) : "f"(v)); return r;
}
__device__ __forceinline__ u64 pk2(float lo, float hi){
    u64 r; asm("mov.b64 %0, {%1,%2};" : "=l"(r) : "f"(lo), "f"(hi)); return r;
}
__device__ __forceinline__ void upk2(u64 v, float &lo, float &hi){
    asm("mov.b64 {%0,%1}, %2;" : "=f"(lo), "=f"(hi) : "l"(v));
}
__device__ __forceinline__ void ffma2(u64 &d, u64 a, u64 b){
    asm("fma.rn.f32x2 %0, %1, %2, %0;" : "+l"(d) : "l"(a), "l"(b));
}
__device__ __forceinline__ void mma16(float &d0, float &d1, float &d2, float &d3,
    uint32_t a0, uint32_t a1, uint32_t a2, uint32_t a3, uint32_t b0, uint32_t b1){
    asm volatile("mma.sync.aligned.m16n8k16.row.col.f32.f16.f16.f32 "
        "{%0,%1,%2,%3},{%4,%5,%6,%7},{%8,%9},{%0,%1,%2,%3};"
        : "+f"(d0),"+f"(d1),"+f"(d2),"+f"(d3)
        : "r"(a0),"r"(a1),"r"(a2),"r"(a3),"r"(b0),"r"(b1));
}

// ---------------- wsplit: fp16 hi/lo, frag-ready layout, k-word permuted ----------------
// within each 8-word k-group: sigma(p) = p<4 ? 2p : 2(p-4)+1  -> frag pairs adjacent
__global__ void __launch_bounds__(1024) wsplit_kernel(
    const float* __restrict__ Whh_f, const float* __restrict__ Whh_b)
{
    const int u = blockIdx.x*1024 + threadIdx.x;
    const int dir = u >> 17;
    const int rem = u & 131071;
    const int nt  = rem >> 14;
    const int rem2 = rem & 16383;
    const int n = rem2 >> 7, kp = rem2 & 127;
    const int k = kp*2;
    const int wrow = (n>>5)*HE + nt*32 + (n&31);
    const float* W = dir ? Whh_b : Whh_f;
    float v0 = __ldg(W + (size_t)wrow*HE + k);
    float v1 = __ldg(W + (size_t)wrow*HE + k + 1);
    __half2 h2 = __floats2half2_rn(v0, v1);
    __half2 l2 = __floats2half2_rn(v0 - __low2float(h2), v1 - __high2float(h2));
    const int p = kp & 7;
    const int kperm = (kp & ~7) | ((p & 3)*2 + (p >> 2));
    const int dst = ((dir*8 + nt)*128 + n)*132 + kperm;
    g_whh[dst] = *(const uint32_t*)&h2;
    g_whl[dst] = *(const uint32_t*)&l2;
}

// ---------------- xproj (exact R6) ----------------
__global__ void __launch_bounds__(256) xproj_kernel(
    const float* __restrict__ x,
    const float* __restrict__ Wih_f, const float* __restrict__ b_f,
    const float* __restrict__ Wih_b, const float* __restrict__ b_b)
{
    extern __shared__ float sxp[];
    float* sWt = sxp;
    float* sXt = sxp + 61*132;
    const int n0  = (blockIdx.x >> 2)*128;
    const int b0  = (blockIdx.x & 3)*128;
    const int pos = blockIdx.y;
    const int dir = blockIdx.z;
    const float* Wih  = dir ? Wih_b : Wih_f;
    const float* bias = dir ? b_b   : b_f;
    const int tid = threadIdx.x, tx = tid&15, ty = tid>>4;

    {
        const int row = tid >> 1, ks = (tid & 1)*32;
        const float* wsrc = Wih + (size_t)(n0+row)*PP;
        const float* xsrc = x + ((size_t)(b0+row)*TT + pos)*PP;
        #pragma unroll
        for (int i=0;i<32;i++){
            int k = ks + i;
            if (k < PP){
                sWt[k*132 + row] = __ldg(wsrc + k);
                sXt[k*132 + row] = __ldg(xsrc + k);
            }
        }
    }
    __syncthreads();

    u64 acc[8][4];
    #pragma unroll
    for (int r=0;r<8;r++)
        #pragma unroll
        for (int c=0;c<4;c++) acc[r][c] = 0ull;

    for (int k=0;k<PP;k++){
        float4 a0 = *(const float4*)&sWt[k*132 + ty*8];
        float4 a1 = *(const float4*)&sWt[k*132 + ty*8 + 4];
        ulonglong2 b0v = *(const ulonglong2*)&sXt[k*132 + tx*8];
        ulonglong2 b1v = *(const ulonglong2*)&sXt[k*132 + tx*8 + 4];
        u64 bd[4] = { b0v.x, b0v.y, b1v.x, b1v.y };
        u64 ad[8] = { pk2(a0.x,a0.x), pk2(a0.y,a0.y), pk2(a0.z,a0.z), pk2(a0.w,a0.w),
                      pk2(a1.x,a1.x), pk2(a1.y,a1.y), pk2(a1.z,a1.z), pk2(a1.w,a1.w) };
        #pragma unroll
        for (int r=0;r<8;r++)
            #pragma unroll
            for (int c=0;c<4;c++) ffma2(acc[r][c], ad[r], bd[c]);
    }

    #pragma unroll
    for (int r=0;r<8;r++){
        const int n = n0 + ty*8 + r;
        const float bv = __ldg(bias + n);
        float* orow = g_xp + (((size_t)dir*TT + pos)*1024 + n)*BB + b0 + tx*8;
        float4 w0, w1;
        upk2(acc[r][0], w0.x, w0.y); upk2(acc[r][1], w0.z, w0.w);
        upk2(acc[r][2], w1.x, w1.y); upk2(acc[r][3], w1.z, w1.w);
        w0.x+=bv; w0.y+=bv; w0.z+=bv; w0.w+=bv;
        w1.x+=bv; w1.y+=bv; w1.z+=bv; w1.w+=bv;
        *(float4*)orow = w0;
        *(float4*)(orow+4) = w1;
    }
}

// ---------------- persistent encoder: fp16 2-pass mma, k-perm frags, fp16 h ----------------
#define SW_H 0
#define SW_L 16896
#define SA_H 33792
#define ENC_SMEM ((33792 + 8448)*4)   // 168960 bytes

__global__ void __launch_bounds__(256, 1) enc_persist_kernel()
{
    extern __shared__ uint32_t smu[];
    __shared__ unsigned s_sense;

    const int bid = blockIdx.x;
    const int dir = bid >> 6;
    const int bt  = (bid >> 3) & 7;
    const int nt  = bid & 7;
    const int b0 = bt*64, j0 = nt*32;
    const int grp = bid >> 3;

    const int tid = threadIdx.x;
    if (tid == 0) s_sense = g_sns[grp];

    {
        const uint32_t* whsrc = g_whh + (size_t)(dir*8 + nt)*16896;
        const uint32_t* wlsrc = g_whl + (size_t)(dir*8 + nt)*16896;
        for (int u = tid; u < 16896; u += 256){
            smu[SW_H + u] = whsrc[u];
            smu[SW_L + u] = wlsrc[u];
        }
    }
    // zero h parity 0 (owned slice)
    for (int i = tid; i < 64*32; i += 256){
        const int r = i >> 5, j = j0 + (i & 31);
        g_h[((dir*2+0)*BB + b0 + r)*HE + j] = __float2half(0.f);
    }

#define GRID_BAR() do {                                            \
        __threadfence();                                           \
        __syncthreads();                                           \
        if (tid == 0){                                             \
            unsigned my = s_sense;                                 \
            unsigned old = atomicAdd(&g_cnt[grp], 1u);             \
            if (old == 7u){                                        \
                g_cnt[grp] = 0;                                    \
                __threadfence();                                   \
                g_sns[grp] = my ^ 1u;                              \
            } else {                                               \
                while (g_sns[grp] == my) __nanosleep(32);          \
            }                                                      \
            s_sense = my ^ 1u;                                     \
        }                                                          \
        __syncthreads();                                           \
    } while(0)

    GRID_BAR();

    const int lane = tid & 31, wid = tid >> 5;
    const int wm = wid & 1, wn = wid >> 1;
    const int g = lane >> 2, t4 = lane & 3;
    const int tx = tid & 31;
    const int ty = tid >> 5;
    const int jj = j0 + tx;

    const int s_row = tid >> 2, s_q = tid & 3;   // s_q covers kp-words [s_q*32, s_q*32+32)

    float creg[8];
    #pragma unroll
    for (int p=0;p<8;p++) creg[p] = 0.f;

    for (int t=0; t<TT; t++){
        const int tpos = dir ? (TT-1-t) : t;
        const int par = t & 1, parn = par ^ 1;
        const __half* hr = g_h + ((size_t)(dir*2+par)*BB + b0 + s_row)*HE;

        // ---- stage h tile: fp16 copy with k-word permutation ----
        // each uint4 = kp words 4q..4q+3; q even -> sigma slots {0,2,4,6}+g*8, odd -> {1,3,5,7}+g*8
        #pragma unroll
        for (int i=0;i<8;i++){
            const int qq = s_q*8 + i;                   // 0..31
            uint4 u = __ldcg(((const uint4*)hr) + qq);
            const int base2 = s_row*132 + (qq>>1)*8 + (qq&1);
            smu[SA_H + base2    ] = u.x;
            smu[SA_H + base2 + 2] = u.y;
            smu[SA_H + base2 + 4] = u.z;
            smu[SA_H + base2 + 6] = u.w;
        }
        __syncthreads();

        // ---- GEMM: 16 k16 groups, 2-pass, LDS.64 frags ----
        float acc[2][4][4];
        #pragma unroll
        for (int a=0;a<2;a++)
            #pragma unroll
            for (int b=0;b<4;b++)
                #pragma unroll
                for (int c=0;c<4;c++) acc[a][b][c] = 0.f;

        #pragma unroll
        for (int kg=0; kg<16; kg++){
            const int base = kg*8;
            uint32_t ah[2][4];
            #pragma unroll
            for (int mt=0;mt<2;mt++){
                const int r = wm*32 + mt*16 + g;
                uint2 aA = *(const uint2*)&smu[SA_H + r    *132 + base + 2*t4];
                uint2 aB = *(const uint2*)&smu[SA_H + (r+8)*132 + base + 2*t4];
                ah[mt][0] = aA.x; ah[mt][2] = aA.y;
                ah[mt][1] = aB.x; ah[mt][3] = aB.y;
            }
            #pragma unroll
            for (int ntI=0;ntI<4;ntI++){
                const int n = wn*32 + ntI*8 + g;
                uint2 bh = *(const uint2*)&smu[SW_H + n*132 + base + 2*t4];
                uint2 bl = *(const uint2*)&smu[SW_L + n*132 + base + 2*t4];
                #pragma unroll
                for (int mt=0;mt<2;mt++){
                    mma16(acc[mt][ntI][0],acc[mt][ntI][1],acc[mt][ntI][2],acc[mt][ntI][3],
                          ah[mt][0],ah[mt][1],ah[mt][2],ah[mt][3], bh.x,bh.y);
                    mma16(acc[mt][ntI][0],acc[mt][ntI][1],acc[mt][ntI][2],acc[mt][ntI][3],
                          ah[mt][0],ah[mt][1],ah[mt][2],ah[mt][3], bl.x,bl.y);
                }
            }
        }
        __syncthreads();

        // ---- C overlays A region ----
        float* Cb = (float*)&smu[SA_H];
        #pragma unroll
        for (int mt=0;mt<2;mt++){
            const int r = wm*32 + mt*16 + g;
            #pragma unroll
            for (int ntI=0;ntI<4;ntI++){
                const int col = wn*32 + ntI*8 + t4*2;
                *(float2*)&Cb[r    *132 + col] = make_float2(acc[mt][ntI][0], acc[mt][ntI][1]);
                *(float2*)&Cb[(r+8)*132 + col] = make_float2(acc[mt][ntI][2], acc[mt][ntI][3]);
            }
        }
        __syncthreads();

        // ---- LSTM cell ----
        const float* xpb = g_xp + ((size_t)dir*TT + tpos)*1024*BB;
        float xg[4][8];
        #pragma unroll
        for (int g2=0; g2<4; g2++){
            float4 xa = __ldg((const float4*)(xpb + (size_t)(g2*HE + jj)*BB + b0 + ty*8));
            float4 xb = __ldg((const float4*)(xpb + (size_t)(g2*HE + jj)*BB + b0 + ty*8 + 4));
            xg[g2][0]=xa.x; xg[g2][1]=xa.y; xg[g2][2]=xa.z; xg[g2][3]=xa.w;
            xg[g2][4]=xb.x; xg[g2][5]=xb.y; xg[g2][6]=xb.z; xg[g2][7]=xb.w;
        }
        #pragma unroll
        for (int p=0;p<8;p++){
            const int r = ty*8 + p;
            float pi = Cb[r*132 +      tx] + xg[0][p];
            float pf = Cb[r*132 + 32 + tx] + xg[1][p];
            float pg = Cb[r*132 + 64 + tx] + xg[2][p];
            float po = Cb[r*132 + 96 + tx] + xg[3][p];
            float iv = sigmoidf_(pi);
            float fv = sigmoidf_(pf);
            float gv = tanh_ap  (pg);
            float ov = sigmoidf_(po);
            float cn = fv*creg[p] + iv*gv;
            creg[p] = cn;
            float hn = ov*tanh_ap(cn);
            const int gb = b0 + r;
            g_enc[((size_t)gb*TT + tpos)*512 + dir*HE + jj] = hn;
            g_h[((size_t)(dir*2+parn)*BB + gb)*HE + jj] = __float2half_rn(hn);
        }

        GRID_BAR();
    }
#undef GRID_BAR
}

// ---------------- encoderOut: fp16 2-pass mma (exact R13) ----------------
#define EF_PAD  20
#define EF_MAT  (128*EF_PAD)
#define EF_STG  (3*EF_MAT)
#define EF_SMEM (2*EF_STG*4)

__global__ void __launch_bounds__(256,1) encout_fp16_kernel(
    const float* __restrict__ Wout, const float* __restrict__ bout,
    float* __restrict__ mu_out, float* __restrict__ lv_out)
{
    extern __shared__ uint32_t smo[];
    const int tid = threadIdx.x, lane = tid & 31, wid = tid >> 5;
    const int wm = wid & 3, wn = wid >> 2;
    const int n0 = blockIdx.x*128, r0 = blockIdx.y*128;
    const int g = lane >> 2, t4 = lane & 3;

    float acc[2][8][4];
    #pragma unroll
    for (int a=0;a<2;a++)
        #pragma unroll
        for (int b=0;b<8;b++)
            #pragma unroll
            for (int c=0;c<4;c++) acc[a][b][c] = 0.f;

    const int srow  = tid >> 1;
    const int shalf = tid & 1;
    const float* asrc = g_enc + (size_t)(r0+srow)*512 + shalf*16;
    const float* bsrc = Wout  + (size_t)(n0+srow)*512 + shalf*16;
    const int sdst = srow*EF_PAD + shalf*8;

    auto sts_hi = [&](uint32_t* hi_base, const float4* v){
        #pragma unroll
        for (int q=0;q<4;q++){
            __half2 h0 = __floats2half2_rn(v[q].x, v[q].y);
            __half2 h1 = __floats2half2_rn(v[q].z, v[q].w);
            *(__half2*)&hi_base[sdst + q*2]     = h0;
            *(__half2*)&hi_base[sdst + q*2 + 1] = h1;
        }
    };
    auto sts_hilo = [&](uint32_t* hi_base, uint32_t* lo_base, const float4* v){
        #pragma unroll
        for (int q=0;q<4;q++){
            __half2 h0 = __floats2half2_rn(v[q].x, v[q].y);
            __half2 h1 = __floats2half2_rn(v[q].z, v[q].w);
            __half2 l0 = __floats2half2_rn(v[q].x - __low2float(h0), v[q].y - __high2float(h0));
            __half2 l1 = __floats2half2_rn(v[q].z - __low2float(h1), v[q].w - __high2float(h1));
            *(__half2*)&hi_base[sdst + q*2]     = h0;
            *(__half2*)&hi_base[sdst + q*2 + 1] = h1;
            *(__half2*)&lo_base[sdst + q*2]     = l0;
            *(__half2*)&lo_base[sdst + q*2 + 1] = l1;
        }
    };

    float4 av[4], bv[4];
    #pragma unroll
    for (int j=0;j<4;j++){ av[j] = __ldg((const float4*)(asrc + j*4)); bv[j] = __ldg((const float4*)(bsrc + j*4)); }
    sts_hi(smo, av);
    sts_hilo(smo + EF_MAT, smo + 2*EF_MAT, bv);
    __syncthreads();

    for (int c=0;c<16;c++){
        if (c+1 < 16){
            #pragma unroll
            for (int j=0;j<4;j++){
                av[j] = __ldg((const float4*)(asrc + (c+1)*32 + j*4));
                bv[j] = __ldg((const float4*)(bsrc + (c+1)*32 + j*4));
            }
        }
        const uint32_t* AH = smo + (c&1)*EF_STG;
        const uint32_t* BH = AH + EF_MAT;
        const uint32_t* BL = AH + 2*EF_MAT;

        #pragma unroll
        for (int ks=0; ks<2; ks++){
            const int base = ks*8;
            uint32_t ah[2][4];
            #pragma unroll
            for (int mt=0;mt<2;mt++){
                const int r = wm*32 + mt*16 + g;
                ah[mt][0] = AH[ r    *EF_PAD + base + t4];
                ah[mt][1] = AH[(r+8) *EF_PAD + base + t4];
                ah[mt][2] = AH[ r    *EF_PAD + base + 4 + t4];
                ah[mt][3] = AH[(r+8) *EF_PAD + base + 4 + t4];
            }
            #pragma unroll
            for (int ntI=0;ntI<8;ntI++){
                const int n = wn*64 + ntI*8 + g;
                uint32_t bh0 = BH[n*EF_PAD + base + t4];
                uint32_t bh1 = BH[n*EF_PAD + base + 4 + t4];
                uint32_t bl0 = BL[n*EF_PAD + base + t4];
                uint32_t bl1 = BL[n*EF_PAD + base + 4 + t4];
                #pragma unroll
                for (int mt=0;mt<2;mt++){
                    mma16(acc[mt][ntI][0],acc[mt][ntI][1],acc[mt][ntI][2],acc[mt][ntI][3],
                          ah[mt][0],ah[mt][1],ah[mt][2],ah[mt][3], bh0,bh1);
                    mma16(acc[mt][ntI][0],acc[mt][ntI][1],acc[mt][ntI][2],acc[mt][ntI][3],
                          ah[mt][0],ah[mt][1],ah[mt][2],ah[mt][3], bl0,bl1);
                }
            }
        }
        if (c+1 < 16){
            uint32_t* NB = smo + ((c+1)&1)*EF_STG;
            sts_hi(NB, av);
            sts_hilo(NB + EF_MAT, NB + 2*EF_MAT, bv);
        }
        __syncthreads();
    }

    #pragma unroll
    for (int mt=0;mt<2;mt++){
        const size_t row = (size_t)r0 + wm*32 + mt*16 + g;
        #pragma unroll
        for (int ntI=0;ntI<8;ntI++){
            const int col = n0 + wn*64 + ntI*8 + t4*2;
            const float bb0 = __ldg(bout + col), bb1 = __ldg(bout + col + 1);
            float v0 = acc[mt][ntI][0] + bb0, v1 = acc[mt][ntI][1] + bb1;
            float v2 = acc[mt][ntI][2] + bb0, v3 = acc[mt][ntI][3] + bb1;
            if (n0 < LATD){
                *(float2*)(mu_out + row*LATD + col)     = make_float2(v0, v1);
                *(float2*)(mu_out + (row+8)*LATD + col) = make_float2(v2, v3);
            } else {
                v0 = (v0>20.f)?v0:log1pf(__expf(v0));
                v1 = (v1>20.f)?v1:log1pf(__expf(v1));
                v2 = (v2>20.f)?v2:log1pf(__expf(v2));
                v3 = (v3>20.f)?v3:log1pf(__expf(v3));
                *(float2*)(lv_out + row*LATD + (col-LATD))     = make_float2(v0, v1);
                *(float2*)(lv_out + (row+8)*LATD + (col-LATD)) = make_float2(v2, v3);
            }
        }
    }
}

// ---------------- z projection (exact R6) ----------------
__global__ void __launch_bounds__(256) zproj_kernel(
    const float* __restrict__ mu, const float* __restrict__ lv, const float* __restrict__ eps,
    const float* __restrict__ Wz, const float* __restrict__ bz, float* __restrict__ zout)
{
    const int r0 = blockIdx.x*128;
    __shared__ float sA[8*132], sB[8*33];
    const int tid = threadIdx.x, tx = tid&15, ty = tid>>4;
    const int m = tid>>1, kb = (tid&1)*4;
    const size_t rr = (size_t)r0 + m;
    const int bidx = (int)(rr >> 8);
    const float* murow  = mu  + rr*LATD;
    const float* lvrow  = lv  + rr*LATD;
    const float* epsrow = eps + (size_t)bidx*LATD;
    const int bnn = tid>>3, bkk = tid&7;

    float acc[8][2] = {};
    float ra[4], rb;
    auto fetch = [&](int k0){
        float4 m4 = *(const float4*)&murow[k0+kb];
        float4 l4 = *(const float4*)&lvrow[k0+kb];
        float4 e4 = *(const float4*)&epsrow[k0+kb];
        ra[0] = m4.x + e4.x*__expf(2.f*l4.x);
        ra[1] = m4.y + e4.y*__expf(2.f*l4.y);
        ra[2] = m4.z + e4.z*__expf(2.f*l4.z);
        ra[3] = m4.w + e4.w*__expf(2.f*l4.w);
        rb = Wz[(size_t)bnn*LATD + k0 + bkk];
    };
    fetch(0);
    for (int ch=0; ch<64; ch++){
        __syncthreads();
        #pragma unroll
        for (int i=0;i<4;i++) sA[(kb+i)*132+m] = ra[i];
        sB[bkk*33 + bnn] = rb;
        __syncthreads();
        if (ch<63) fetch((ch+1)*8);
        #pragma unroll
        for (int kk=0;kk<8;kk++){
            float4 a0 = *(const float4*)&sA[kk*132 + ty*8];
            float4 a1 = *(const float4*)&sA[kk*132 + ty*8 + 4];
            float a[8] = {a0.x,a0.y,a0.z,a0.w,a1.x,a1.y,a1.z,a1.w};
            float bv0 = sB[kk*33 + tx*2 + 0];
            float bv1 = sB[kk*33 + tx*2 + 1];
            #pragma unroll
            for (int r=0;r<8;r++){
                acc[r][0] = fmaf(a[r], bv0, acc[r][0]);
                acc[r][1] = fmaf(a[r], bv1, acc[r][1]);
            }
        }
    }
    #pragma unroll
    for (int ri=0;ri<8;ri++){
        const size_t r = r0 + ty*8 + ri;
        #pragma unroll
        for (int ci=0;ci<2;ci++){
            const int col = tx*2 + ci;
            zout[r*DECD + col] = acc[ri][ci] + bz[col];
        }
    }
}

// ---------------- conductor LSTM (exact R6) ----------------
__global__ void __launch_bounds__(256) conductor_kernel(
    const float* __restrict__ zout, const float* __restrict__ Wih,
    const float* __restrict__ Whh, const float* __restrict__ bias)
{
    __shared__ float sWi[128*33], sWh[128*33], sb[128];
    __shared__ float sh[8*33], sc[8*33], sz[8*33];
    const int tid = threadIdx.x;
    const int b0 = blockIdx.x*8;
    for (int i=tid; i<128*32; i+=256){ int cc=i>>5, k=i&31; sWi[cc*33+k]=Wih[i]; sWh[cc*33+k]=Whh[i]; }
    if (tid < 128) sb[tid] = bias[tid];
    { int mm=tid>>5, k=tid&31; sh[mm*33+k]=0.f; sc[mm*33+k]=0.f; }
    __syncthreads();

    const int j  = tid & 31;
    const int m  = tid >> 5;
    for (int t=0; t<TBAR; t++){
        { int mm=tid>>5, k=tid&31;
          sz[mm*33+k] = zout[((size_t)(b0+mm)*TT + t)*DECD + k]; }
        __syncthreads();
        float a0=sb[j], a1=sb[32+j], a2=sb[64+j], a3=sb[96+j];
        #pragma unroll
        for (int k=0;k<32;k++){
            float zv = sz[m*33+k], hv = sh[m*33+k];
            a0 += zv*sWi[( j   )*33+k] + hv*sWh[( j   )*33+k];
            a1 += zv*sWi[(32+j)*33+k]  + hv*sWh[(32+j)*33+k];
            a2 += zv*sWi[(64+j)*33+k]  + hv*sWh[(64+j)*33+k];
            a3 += zv*sWi[(96+j)*33+k]  + hv*sWh[(96+j)*33+k];
        }
        float iv=sigmoidf_(a0), fv=sigmoidf_(a1), gv=tanhf(a2), ov=sigmoidf_(a3);
        float cn = fv*sc[m*33+j] + iv*gv;
        float hn = ov*tanhf(cn);
        __syncthreads();
        sh[m*33+j]=hn; sc[m*33+j]=cn;
        g_emb[((size_t)(b0+m)*TBAR + t)*DECD + j] = hn;
        __syncthreads();
    }
}

// ---------------- decoder (exact R6) ----------------
__global__ void __launch_bounds__(256) decoder_kernel(
    const float* __restrict__ x, const float* __restrict__ h0in, const float* __restrict__ c0in,
    const float* __restrict__ Wih, const float* __restrict__ Whh, const float* __restrict__ bias,
    const float* __restrict__ Wlin, const float* __restrict__ blin,
    float* __restrict__ notes)
{
    extern __shared__ float smd[];
    float* sWi = smd;
    float* sWh = sWi + 128*93;
    float* sb  = sWh + 128*33;
    float* sWl = sb + 128;
    float* sbl = sWl + 64*33;
    const int tid = threadIdx.x;
    for (int i=tid; i<128*93; i+=256) sWi[i] = Wih[i];
    for (int i=tid; i<128*32; i+=256){ int cc=i>>5, k=i&31; sWh[cc*33+k] = Whh[i]; }
    if (tid < 128) sb[tid] = bias[tid];
    for (int i=tid; i<64*32; i+=256){ int cc=i>>5, k=i&31; sWl[cc*33+k] = (cc<PP) ? Wlin[i] : 0.f; }
    if (tid < 64) sbl[tid] = (tid<PP) ? blin[tid] : 0.f;
    __syncthreads();

    const int w = tid>>5, lane = tid&31;
    const int row  = blockIdx.x*8 + w;
    const int bidx = row>>4, bar = row&15;
    float h = h0in[((size_t)bar*BB + bidx)*DECD + lane];
    float c = c0in[((size_t)bar*BB + bidx)*DECD + lane];
    const float emb = g_emb[(size_t)row*DECD + lane];
    const unsigned FULL = 0xffffffffu;
    const int c0_=lane, c1_=32+lane, c2_=64+lane, c3_=96+lane;

    for (int n=0;n<16;n++){
        const int time = bar*16 + n;
        float t0 = 0.f, t1 = 0.f;
        if (time > 0){
            const float* xr = x + ((size_t)bidx*TT + time-1)*PP;
            t0 = xr[lane];
            if (lane < 29) t1 = xr[32+lane];
        }
        float a0=sb[c0_], a1=sb[c1_], a2=sb[c2_], a3=sb[c3_];
        #pragma unroll
        for (int k=0;k<32;k++){
            float av = __shfl_sync(FULL, emb, k);
            a0 = fmaf(av, sWi[c0_*93+k], a0); a1 = fmaf(av, sWi[c1_*93+k], a1);
            a2 = fmaf(av, sWi[c2_*93+k], a2); a3 = fmaf(av, sWi[c3_*93+k], a3);
        }
        #pragma unroll
        for (int k=0;k<32;k++){
            float av = __shfl_sync(FULL, t0, k); const int kk=32+k;
            a0 = fmaf(av, sWi[c0_*93+kk], a0); a1 = fmaf(av, sWi[c1_*93+kk], a1);
            a2 = fmaf(av, sWi[c2_*93+kk], a2); a3 = fmaf(av, sWi[c3_*93+kk], a3);
        }
        #pragma unroll
        for (int k=0;k<29;k++){
            float av = __shfl_sync(FULL, t1, k); const int kk=64+k;
            a0 = fmaf(av, sWi[c0_*93+kk], a0); a1 = fmaf(av, sWi[c1_*93+kk], a1);
            a2 = fmaf(av, sWi[c2_*93+kk], a2); a3 = fmaf(av, sWi[c3_*93+kk], a3);
        }
        #pragma unroll
        for (int k=0;k<32;k++){
            float av = __shfl_sync(FULL, h, k);
            a0 = fmaf(av, sWh[c0_*33+k], a0); a1 = fmaf(av, sWh[c1_*33+k], a1);
            a2 = fmaf(av, sWh[c2_*33+k], a2); a3 = fmaf(av, sWh[c3_*33+k], a3);
        }
        float iv=sigmoidf_(a0), fv=sigmoidf_(a1), gv=tanhf(a2), ov=sigmoidf_(a3);
        c = fv*c + iv*gv;
        h = ov*tanhf(c);

        float l0 = sbl[lane], l1 = sbl[32+lane];
        #pragma unroll
        for (int k=0;k<32;k++){
            float hv = __shfl_sync(FULL, h, k);
            l0 = fmaf(hv, sWl[lane*33+k], l0);
            l1 = fmaf(hv, sWl[(32+lane)*33+k], l1);
        }
        float l1m = (lane < 29) ? l1 : -1e30f;
        float mx = fmaxf(l0, l1m);
        #pragma unroll
        for (int off=16; off; off>>=1) mx = fmaxf(mx, __shfl_xor_sync(FULL, mx, off));
        float e0 = __expf(l0 - mx);
        float e1 = (lane < 29) ? __expf(l1 - mx) : 0.f;
        float s = e0 + e1;
        #pragma unroll
        for (int off=16; off; off>>=1) s += __shfl_xor_sync(FULL, s, off);
        const float inv = 1.f/s;
        float* nr = notes + ((size_t)bidx*TT + time)*PP;
        nr[lane] = e0*inv;
        if (lane < 29) nr[32+lane] = e1*inv;
    }
}

// ---------------- launch ----------------
extern "C" void kernel_launch(void* const* d_in, const int* in_sizes, int n_in,
                              void* d_out, int out_size)
{
    const float* x        = (const float*)d_in[0];
    const float* eps      = (const float*)d_in[1];
    const float* dec_h0   = (const float*)d_in[2];
    const float* dec_c0   = (const float*)d_in[3];
    const float* eWih_f   = (const float*)d_in[4];
    const float* eWhh_f   = (const float*)d_in[5];
    const float* eb_f     = (const float*)d_in[6];
    const float* eWih_b   = (const float*)d_in[7];
    const float* eWhh_b   = (const float*)d_in[8];
    const float* eb_b     = (const float*)d_in[9];
    const float* Wout     = (const float*)d_in[10];
    const float* bout     = (const float*)d_in[11];
    const float* Wz       = (const float*)d_in[12];
    const float* bz       = (const float*)d_in[13];
    const float* conWih   = (const float*)d_in[14];
    const float* conWhh   = (const float*)d_in[15];
    const float* conb     = (const float*)d_in[16];
    const float* dWih     = (const float*)d_in[17];
    const float* dWhh     = (const float*)d_in[18];
    const float* db       = (const float*)d_in[19];
    const float* Wlin     = (const float*)d_in[20];
    const float* blin     = (const float*)d_in[21];

    float* out   = (float*)d_out;
    float* notes = out;
    float* zout  = out + (size_t)NROWS*PP;
    float* muo   = zout + (size_t)NROWS*DECD;
    float* lvo   = muo  + (size_t)NROWS*LATD;

    wsplit_kernel<<<256, 1024>>>(eWhh_f, eWhh_b);

    cudaFuncSetAttribute(xproj_kernel, cudaFuncAttributeMaxDynamicSharedMemorySize, 66048);
    xproj_kernel<<<dim3(32, TT, 2), 256, 66048>>>(x, eWih_f, eb_f, eWih_b, eb_b);

    cudaFuncSetAttribute(enc_persist_kernel, cudaFuncAttributeMaxDynamicSharedMemorySize, ENC_SMEM);
    enc_persist_kernel<<<NBLK, 256, ENC_SMEM>>>();

    cudaFuncSetAttribute(encout_fp16_kernel, cudaFuncAttributeMaxDynamicSharedMemorySize, EF_SMEM);
    encout_fp16_kernel<<<dim3(8, NROWS/128), 256, EF_SMEM>>>(Wout, bout, muo, lvo);

    zproj_kernel<<<NROWS/128, 256>>>(muo, lvo, eps, Wz, bz, zout);

    conductor_kernel<<<BB/8, 256>>>(zout, conWih, conWhh, conb);

    cudaFuncSetAttribute(decoder_kernel, cudaFuncAttributeMaxDynamicSharedMemorySize, 73728);
    decoder_kernel<<<(BB*TBAR)/8, 256, 73728>>>(x, dec_h0, dec_c0,
                                                dWih, dWhh, db, Wlin, blin, notes);
}

// round 15
// speedup vs baseline: 1.1193x; 1.1193x over previous
#include <cuda_runtime.h>
#include <cuda_fp16.h>
#include <math.h>
#include <stdint.h>

#define BB   512
#define TT   256
#define PP   61
#define HE   256
#define LATD 512
#define DECD 32
#define TBAR 16
#define NROWS (BB*TT)   // 131072
#define NBLK 128

// ---------------- scratch ----------------
__device__ float g_enc[(size_t)NROWS*512];          // (B*T, 2H)
__device__ float g_xp[(size_t)2*TT*1024*BB];        // [dir][pos][n][b]
__device__ float g_h[2*2*BB*HE];                    // [dir][parity][b][j]
__device__ float g_emb[(size_t)BB*TBAR*DECD];
__device__ uint32_t g_whh[270336];                  // [dir][nt][n 128][kp 132] fp16x2 hi
__device__ uint32_t g_whl[270336];                  // fp16x2 lo

__device__ unsigned g_cnt[16];
__device__ volatile unsigned g_sns[16];

typedef unsigned long long u64;

__device__ __forceinline__ float sigmoidf_(float v){ return 1.f/(1.f+__expf(-v)); }
__device__ __forceinline__ float tanh_ap(float v){
    float r; asm("tanh.approx.f32 %0, %1;" : "=f"(r) : "f"(v)); return r;
}
__device__ __forceinline__ u64 pk2(float lo, float hi){
    u64 r; asm("mov.b64 %0, {%1,%2};" : "=l"(r) : "f"(lo), "f"(hi)); return r;
}
__device__ __forceinline__ void upk2(u64 v, float &lo, float &hi){
    asm("mov.b64 {%0,%1}, %2;" : "=f"(lo), "=f"(hi) : "l"(v));
}
__device__ __forceinline__ void ffma2(u64 &d, u64 a, u64 b){
    asm("fma.rn.f32x2 %0, %1, %2, %0;" : "+l"(d) : "l"(a), "l"(b));
}
__device__ __forceinline__ void mma16(float &d0, float &d1, float &d2, float &d3,
    uint32_t a0, uint32_t a1, uint32_t a2, uint32_t a3, uint32_t b0, uint32_t b1){
    asm volatile("mma.sync.aligned.m16n8k16.row.col.f32.f16.f16.f32 "
        "{%0,%1,%2,%3},{%4,%5,%6,%7},{%8,%9},{%0,%1,%2,%3};"
        : "+f"(d0),"+f"(d1),"+f"(d2),"+f"(d3)
        : "r"(a0),"r"(a1),"r"(a2),"r"(a3),"r"(b0),"r"(b1));
}

// ---------------- wsplit (exact R13, no perm) ----------------
__global__ void __launch_bounds__(1024) wsplit_kernel(
    const float* __restrict__ Whh_f, const float* __restrict__ Whh_b)
{
    const int u = blockIdx.x*1024 + threadIdx.x;
    const int dir = u >> 17;
    const int rem = u & 131071;
    const int nt  = rem >> 14;
    const int rem2 = rem & 16383;
    const int n = rem2 >> 7, kp = rem2 & 127;
    const int k = kp*2;
    const int wrow = (n>>5)*HE + nt*32 + (n&31);
    const float* W = dir ? Whh_b : Whh_f;
    float v0 = __ldg(W + (size_t)wrow*HE + k);
    float v1 = __ldg(W + (size_t)wrow*HE + k + 1);
    __half2 h2 = __floats2half2_rn(v0, v1);
    __half2 l2 = __floats2half2_rn(v0 - __low2float(h2), v1 - __high2float(h2));
    const int dst = ((dir*8 + nt)*128 + n)*132 + kp;
    g_whh[dst] = *(const uint32_t*)&h2;
    g_whl[dst] = *(const uint32_t*)&l2;
}

// ---------------- xproj (exact R6) ----------------
__global__ void __launch_bounds__(256) xproj_kernel(
    const float* __restrict__ x,
    const float* __restrict__ Wih_f, const float* __restrict__ b_f,
    const float* __restrict__ Wih_b, const float* __restrict__ b_b)
{
    extern __shared__ float sxp[];
    float* sWt = sxp;
    float* sXt = sxp + 61*132;
    const int n0  = (blockIdx.x >> 2)*128;
    const int b0  = (blockIdx.x & 3)*128;
    const int pos = blockIdx.y;
    const int dir = blockIdx.z;
    const float* Wih  = dir ? Wih_b : Wih_f;
    const float* bias = dir ? b_b   : b_f;
    const int tid = threadIdx.x, tx = tid&15, ty = tid>>4;

    {
        const int row = tid >> 1, ks = (tid & 1)*32;
        const float* wsrc = Wih + (size_t)(n0+row)*PP;
        const float* xsrc = x + ((size_t)(b0+row)*TT + pos)*PP;
        #pragma unroll
        for (int i=0;i<32;i++){
            int k = ks + i;
            if (k < PP){
                sWt[k*132 + row] = __ldg(wsrc + k);
                sXt[k*132 + row] = __ldg(xsrc + k);
            }
        }
    }
    __syncthreads();

    u64 acc[8][4];
    #pragma unroll
    for (int r=0;r<8;r++)
        #pragma unroll
        for (int c=0;c<4;c++) acc[r][c] = 0ull;

    for (int k=0;k<PP;k++){
        float4 a0 = *(const float4*)&sWt[k*132 + ty*8];
        float4 a1 = *(const float4*)&sWt[k*132 + ty*8 + 4];
        ulonglong2 b0v = *(const ulonglong2*)&sXt[k*132 + tx*8];
        ulonglong2 b1v = *(const ulonglong2*)&sXt[k*132 + tx*8 + 4];
        u64 bd[4] = { b0v.x, b0v.y, b1v.x, b1v.y };
        u64 ad[8] = { pk2(a0.x,a0.x), pk2(a0.y,a0.y), pk2(a0.z,a0.z), pk2(a0.w,a0.w),
                      pk2(a1.x,a1.x), pk2(a1.y,a1.y), pk2(a1.z,a1.z), pk2(a1.w,a1.w) };
        #pragma unroll
        for (int r=0;r<8;r++)
            #pragma unroll
            for (int c=0;c<4;c++) ffma2(acc[r][c], ad[r], bd[c]);
    }

    #pragma unroll
    for (int r=0;r<8;r++){
        const int n = n0 + ty*8 + r;
        const float bv = __ldg(bias + n);
        float* orow = g_xp + (((size_t)dir*TT + pos)*1024 + n)*BB + b0 + tx*8;
        float4 w0, w1;
        upk2(acc[r][0], w0.x, w0.y); upk2(acc[r][1], w0.z, w0.w);
        upk2(acc[r][2], w1.x, w1.y); upk2(acc[r][3], w1.z, w1.w);
        w0.x+=bv; w0.y+=bv; w0.z+=bv; w0.w+=bv;
        w1.x+=bv; w1.y+=bv; w1.z+=bv; w1.w+=bv;
        *(float4*)orow = w0;
        *(float4*)(orow+4) = w1;
    }
}

// ---------------- persistent encoder: fp16 2-pass mma, 512 threads (16 warps) ----------------
#define SW_H 0
#define SW_L 16896
#define SA_H 33792
#define ENC_SMEM ((33792 + 8448)*4)   // 168960 bytes

__global__ void __launch_bounds__(512, 1) enc_persist_kernel()
{
    extern __shared__ uint32_t smu[];
    __shared__ unsigned s_sense;

    const int bid = blockIdx.x;
    const int dir = bid >> 6;
    const int bt  = (bid >> 3) & 7;
    const int nt  = bid & 7;
    const int b0 = bt*64, j0 = nt*32;
    const int grp = bid >> 3;

    const int tid = threadIdx.x;
    if (tid == 0) s_sense = g_sns[grp];

    {
        const uint32_t* whsrc = g_whh + (size_t)(dir*8 + nt)*16896;
        const uint32_t* wlsrc = g_whl + (size_t)(dir*8 + nt)*16896;
        for (int u = tid; u < 16896; u += 512){
            smu[SW_H + u] = whsrc[u];
            smu[SW_L + u] = wlsrc[u];
        }
    }
    for (int i = tid; i < 64*32; i += 512){
        const int r = i >> 5, j = j0 + (i & 31);
        g_h[((dir*2+0)*BB + b0 + r)*HE + j] = 0.f;
    }

#define GRID_BAR() do {                                            \
        __threadfence();                                           \
        __syncthreads();                                           \
        if (tid == 0){                                             \
            unsigned my = s_sense;                                 \
            unsigned old = atomicAdd(&g_cnt[grp], 1u);             \
            if (old == 7u){                                        \
                g_cnt[grp] = 0;                                    \
                __threadfence();                                   \
                g_sns[grp] = my ^ 1u;                              \
            } else {                                               \
                while (g_sns[grp] == my) __nanosleep(32);          \
            }                                                      \
            s_sense = my ^ 1u;                                     \
        }                                                          \
        __syncthreads();                                           \
    } while(0)

    GRID_BAR();

    const int lane = tid & 31, wid = tid >> 5;
    const int wm = wid & 1, wn = wid >> 1;      // 2 row-halves x 8 n-slices(16)
    const int g = lane >> 2, t4 = lane & 3;
    const int tx = tid & 31;                    // cell: j local
    const int ty = tid >> 5;                    // cell: row group of 4 (0..15)
    const int jj = j0 + tx;

    const int s_row = tid >> 3, s_q = tid & 7;  // staging: 8 threads/row

    float creg[4] = {0.f, 0.f, 0.f, 0.f};

    for (int t=0; t<TT; t++){
        const int tpos = dir ? (TT-1-t) : t;
        const int par = t & 1, parn = par ^ 1;
        const float* hr = g_h + ((size_t)(dir*2+par)*BB + b0 + s_row)*HE;

        // ---- stage h tile (64 x 256) -> fp16 hi (R13 scheme, 512-thread stride) ----
        #pragma unroll
        for (int i=0;i<8;i++){
            const int j = s_q*4 + i*32;
            float4 v = __ldcg((const float4*)(hr + j));
            __half2 h0 = __floats2half2_rn(v.x, v.y);
            __half2 h1 = __floats2half2_rn(v.z, v.w);
            uint2 hw = make_uint2(*(const uint32_t*)&h0, *(const uint32_t*)&h1);
            *(uint2*)&smu[SA_H + s_row*132 + (j>>1)] = hw;
        }
        __syncthreads();

        // ---- GEMM: 16 k16 groups, 2-pass; each warp: 2 m-frags x 2 n-frags ----
        float acc[2][2][4];
        #pragma unroll
        for (int a=0;a<2;a++)
            #pragma unroll
            for (int b=0;b<2;b++)
                #pragma unroll
                for (int c=0;c<4;c++) acc[a][b][c] = 0.f;

        #pragma unroll
        for (int kg=0; kg<16; kg++){
            const int base = kg*8;
            uint32_t ah[2][4];
            #pragma unroll
            for (int mt=0;mt<2;mt++){
                const int r = wm*32 + mt*16 + g;
                ah[mt][0] = smu[SA_H + r    *132 + base + t4];
                ah[mt][1] = smu[SA_H + (r+8)*132 + base + t4];
                ah[mt][2] = smu[SA_H + r    *132 + base + 4 + t4];
                ah[mt][3] = smu[SA_H + (r+8)*132 + base + 4 + t4];
            }
            #pragma unroll
            for (int ntI=0;ntI<2;ntI++){
                const int n = wn*16 + ntI*8 + g;
                uint32_t bh0 = smu[SW_H + n*132 + base + t4];
                uint32_t bh1 = smu[SW_H + n*132 + base + 4 + t4];
                uint32_t bl0 = smu[SW_L + n*132 + base + t4];
                uint32_t bl1 = smu[SW_L + n*132 + base + 4 + t4];
                #pragma unroll
                for (int mt=0;mt<2;mt++){
                    mma16(acc[mt][ntI][0],acc[mt][ntI][1],acc[mt][ntI][2],acc[mt][ntI][3],
                          ah[mt][0],ah[mt][1],ah[mt][2],ah[mt][3], bh0,bh1);
                    mma16(acc[mt][ntI][0],acc[mt][ntI][1],acc[mt][ntI][2],acc[mt][ntI][3],
                          ah[mt][0],ah[mt][1],ah[mt][2],ah[mt][3], bl0,bl1);
                }
            }
        }
        __syncthreads();

        // ---- C overlays A region ----
        float* Cb = (float*)&smu[SA_H];
        #pragma unroll
        for (int mt=0;mt<2;mt++){
            const int r = wm*32 + mt*16 + g;
            #pragma unroll
            for (int ntI=0;ntI<2;ntI++){
                const int col = wn*16 + ntI*8 + t4*2;
                *(float2*)&Cb[r    *132 + col] = make_float2(acc[mt][ntI][0], acc[mt][ntI][1]);
                *(float2*)&Cb[(r+8)*132 + col] = make_float2(acc[mt][ntI][2], acc[mt][ntI][3]);
            }
        }
        __syncthreads();

        // ---- LSTM cell: 4 rows per thread ----
        const float* xpb = g_xp + ((size_t)dir*TT + tpos)*1024*BB;
        float4 xg[4];
        #pragma unroll
        for (int g2=0; g2<4; g2++)
            xg[g2] = __ldg((const float4*)(xpb + (size_t)(g2*HE + jj)*BB + b0 + ty*4));
        #pragma unroll
        for (int p=0;p<4;p++){
            const int r = ty*4 + p;
            float pi = Cb[r*132 +      tx] + ((const float*)&xg[0])[p];
            float pf = Cb[r*132 + 32 + tx] + ((const float*)&xg[1])[p];
            float pg = Cb[r*132 + 64 + tx] + ((const float*)&xg[2])[p];
            float po = Cb[r*132 + 96 + tx] + ((const float*)&xg[3])[p];
            float iv = sigmoidf_(pi);
            float fv = sigmoidf_(pf);
            float gv = tanh_ap  (pg);
            float ov = sigmoidf_(po);
            float cn = fv*creg[p] + iv*gv;
            creg[p] = cn;
            float hn = ov*tanh_ap(cn);
            const int gb = b0 + r;
            g_enc[((size_t)gb*TT + tpos)*512 + dir*HE + jj] = hn;
            g_h[((size_t)(dir*2+parn)*BB + gb)*HE + jj] = hn;
        }

        GRID_BAR();
    }
#undef GRID_BAR
}

// ---------------- encoderOut: fp16 2-pass mma (exact R13) ----------------
#define EF_PAD  20
#define EF_MAT  (128*EF_PAD)
#define EF_STG  (3*EF_MAT)
#define EF_SMEM (2*EF_STG*4)

__global__ void __launch_bounds__(256,1) encout_fp16_kernel(
    const float* __restrict__ Wout, const float* __restrict__ bout,
    float* __restrict__ mu_out, float* __restrict__ lv_out)
{
    extern __shared__ uint32_t smo[];
    const int tid = threadIdx.x, lane = tid & 31, wid = tid >> 5;
    const int wm = wid & 3, wn = wid >> 2;
    const int n0 = blockIdx.x*128, r0 = blockIdx.y*128;
    const int g = lane >> 2, t4 = lane & 3;

    float acc[2][8][4];
    #pragma unroll
    for (int a=0;a<2;a++)
        #pragma unroll
        for (int b=0;b<8;b++)
            #pragma unroll
            for (int c=0;c<4;c++) acc[a][b][c] = 0.f;

    const int srow  = tid >> 1;
    const int shalf = tid & 1;
    const float* asrc = g_enc + (size_t)(r0+srow)*512 + shalf*16;
    const float* bsrc = Wout  + (size_t)(n0+srow)*512 + shalf*16;
    const int sdst = srow*EF_PAD + shalf*8;

    auto sts_hi = [&](uint32_t* hi_base, const float4* v){
        #pragma unroll
        for (int q=0;q<4;q++){
            __half2 h0 = __floats2half2_rn(v[q].x, v[q].y);
            __half2 h1 = __floats2half2_rn(v[q].z, v[q].w);
            *(__half2*)&hi_base[sdst + q*2]     = h0;
            *(__half2*)&hi_base[sdst + q*2 + 1] = h1;
        }
    };
    auto sts_hilo = [&](uint32_t* hi_base, uint32_t* lo_base, const float4* v){
        #pragma unroll
        for (int q=0;q<4;q++){
            __half2 h0 = __floats2half2_rn(v[q].x, v[q].y);
            __half2 h1 = __floats2half2_rn(v[q].z, v[q].w);
            __half2 l0 = __floats2half2_rn(v[q].x - __low2float(h0), v[q].y - __high2float(h0));
            __half2 l1 = __floats2half2_rn(v[q].z - __low2float(h1), v[q].w - __high2float(h1));
            *(__half2*)&hi_base[sdst + q*2]     = h0;
            *(__half2*)&hi_base[sdst + q*2 + 1] = h1;
            *(__half2*)&lo_base[sdst + q*2]     = l0;
            *(__half2*)&lo_base[sdst + q*2 + 1] = l1;
        }
    };

    float4 av[4], bv[4];
    #pragma unroll
    for (int j=0;j<4;j++){ av[j] = __ldg((const float4*)(asrc + j*4)); bv[j] = __ldg((const float4*)(bsrc + j*4)); }
    sts_hi(smo, av);
    sts_hilo(smo + EF_MAT, smo + 2*EF_MAT, bv);
    __syncthreads();

    for (int c=0;c<16;c++){
        if (c+1 < 16){
            #pragma unroll
            for (int j=0;j<4;j++){
                av[j] = __ldg((const float4*)(asrc + (c+1)*32 + j*4));
                bv[j] = __ldg((const float4*)(bsrc + (c+1)*32 + j*4));
            }
        }
        const uint32_t* AH = smo + (c&1)*EF_STG;
        const uint32_t* BH = AH + EF_MAT;
        const uint32_t* BL = AH + 2*EF_MAT;

        #pragma unroll
        for (int ks=0; ks<2; ks++){
            const int base = ks*8;
            uint32_t ah[2][4];
            #pragma unroll
            for (int mt=0;mt<2;mt++){
                const int r = wm*32 + mt*16 + g;
                ah[mt][0] = AH[ r    *EF_PAD + base + t4];
                ah[mt][1] = AH[(r+8) *EF_PAD + base + t4];
                ah[mt][2] = AH[ r    *EF_PAD + base + 4 + t4];
                ah[mt][3] = AH[(r+8) *EF_PAD + base + 4 + t4];
            }
            #pragma unroll
            for (int ntI=0;ntI<8;ntI++){
                const int n = wn*64 + ntI*8 + g;
                uint32_t bh0 = BH[n*EF_PAD + base + t4];
                uint32_t bh1 = BH[n*EF_PAD + base + 4 + t4];
                uint32_t bl0 = BL[n*EF_PAD + base + t4];
                uint32_t bl1 = BL[n*EF_PAD + base + 4 + t4];
                #pragma unroll
                for (int mt=0;mt<2;mt++){
                    mma16(acc[mt][ntI][0],acc[mt][ntI][1],acc[mt][ntI][2],acc[mt][ntI][3],
                          ah[mt][0],ah[mt][1],ah[mt][2],ah[mt][3], bh0,bh1);
                    mma16(acc[mt][ntI][0],acc[mt][ntI][1],acc[mt][ntI][2],acc[mt][ntI][3],
                          ah[mt][0],ah[mt][1],ah[mt][2],ah[mt][3], bl0,bl1);
                }
            }
        }
        if (c+1 < 16){
            uint32_t* NB = smo + ((c+1)&1)*EF_STG;
            sts_hi(NB, av);
            sts_hilo(NB + EF_MAT, NB + 2*EF_MAT, bv);
        }
        __syncthreads();
    }

    #pragma unroll
    for (int mt=0;mt<2;mt++){
        const size_t row = (size_t)r0 + wm*32 + mt*16 + g;
        #pragma unroll
        for (int ntI=0;ntI<8;ntI++){
            const int col = n0 + wn*64 + ntI*8 + t4*2;
            const float bb0 = __ldg(bout + col), bb1 = __ldg(bout + col + 1);
            float v0 = acc[mt][ntI][0] + bb0, v1 = acc[mt][ntI][1] + bb1;
            float v2 = acc[mt][ntI][2] + bb0, v3 = acc[mt][ntI][3] + bb1;
            if (n0 < LATD){
                *(float2*)(mu_out + row*LATD + col)     = make_float2(v0, v1);
                *(float2*)(mu_out + (row+8)*LATD + col) = make_float2(v2, v3);
            } else {
                v0 = (v0>20.f)?v0:log1pf(__expf(v0));
                v1 = (v1>20.f)?v1:log1pf(__expf(v1));
                v2 = (v2>20.f)?v2:log1pf(__expf(v2));
                v3 = (v3>20.f)?v3:log1pf(__expf(v3));
                *(float2*)(lv_out + row*LATD + (col-LATD))     = make_float2(v0, v1);
                *(float2*)(lv_out + (row+8)*LATD + (col-LATD)) = make_float2(v2, v3);
            }
        }
    }
}

// ---------------- z projection (exact R6) ----------------
__global__ void __launch_bounds__(256) zproj_kernel(
    const float* __restrict__ mu, const float* __restrict__ lv, const float* __restrict__ eps,
    const float* __restrict__ Wz, const float* __restrict__ bz, float* __restrict__ zout)
{
    const int r0 = blockIdx.x*128;
    __shared__ float sA[8*132], sB[8*33];
    const int tid = threadIdx.x, tx = tid&15, ty = tid>>4;
    const int m = tid>>1, kb = (tid&1)*4;
    const size_t rr = (size_t)r0 + m;
    const int bidx = (int)(rr >> 8);
    const float* murow  = mu  + rr*LATD;
    const float* lvrow  = lv  + rr*LATD;
    const float* epsrow = eps + (size_t)bidx*LATD;
    const int bnn = tid>>3, bkk = tid&7;

    float acc[8][2] = {};
    float ra[4], rb;
    auto fetch = [&](int k0){
        float4 m4 = *(const float4*)&murow[k0+kb];
        float4 l4 = *(const float4*)&lvrow[k0+kb];
        float4 e4 = *(const float4*)&epsrow[k0+kb];
        ra[0] = m4.x + e4.x*__expf(2.f*l4.x);
        ra[1] = m4.y + e4.y*__expf(2.f*l4.y);
        ra[2] = m4.z + e4.z*__expf(2.f*l4.z);
        ra[3] = m4.w + e4.w*__expf(2.f*l4.w);
        rb = Wz[(size_t)bnn*LATD + k0 + bkk];
    };
    fetch(0);
    for (int ch=0; ch<64; ch++){
        __syncthreads();
        #pragma unroll
        for (int i=0;i<4;i++) sA[(kb+i)*132+m] = ra[i];
        sB[bkk*33 + bnn] = rb;
        __syncthreads();
        if (ch<63) fetch((ch+1)*8);
        #pragma unroll
        for (int kk=0;kk<8;kk++){
            float4 a0 = *(const float4*)&sA[kk*132 + ty*8];
            float4 a1 = *(const float4*)&sA[kk*132 + ty*8 + 4];
            float a[8] = {a0.x,a0.y,a0.z,a0.w,a1.x,a1.y,a1.z,a1.w};
            float bv0 = sB[kk*33 + tx*2 + 0];
            float bv1 = sB[kk*33 + tx*2 + 1];
            #pragma unroll
            for (int r=0;r<8;r++){
                acc[r][0] = fmaf(a[r], bv0, acc[r][0]);
                acc[r][1] = fmaf(a[r], bv1, acc[r][1]);
            }
        }
    }
    #pragma unroll
    for (int ri=0;ri<8;ri++){
        const size_t r = r0 + ty*8 + ri;
        #pragma unroll
        for (int ci=0;ci<2;ci++){
            const int col = tx*2 + ci;
            zout[r*DECD + col] = acc[ri][ci] + bz[col];
        }
    }
}

// ---------------- conductor LSTM (exact R6) ----------------
__global__ void __launch_bounds__(256) conductor_kernel(
    const float* __restrict__ zout, const float* __restrict__ Wih,
    const float* __restrict__ Whh, const float* __restrict__ bias)
{
    __shared__ float sWi[128*33], sWh[128*33], sb[128];
    __shared__ float sh[8*33], sc[8*33], sz[8*33];
    const int tid = threadIdx.x;
    const int b0 = blockIdx.x*8;
    for (int i=tid; i<128*32; i+=256){ int cc=i>>5, k=i&31; sWi[cc*33+k]=Wih[i]; sWh[cc*33+k]=Whh[i]; }
    if (tid < 128) sb[tid] = bias[tid];
    { int mm=tid>>5, k=tid&31; sh[mm*33+k]=0.f; sc[mm*33+k]=0.f; }
    __syncthreads();

    const int j  = tid & 31;
    const int m  = tid >> 5;
    for (int t=0; t<TBAR; t++){
        { int mm=tid>>5, k=tid&31;
          sz[mm*33+k] = zout[((size_t)(b0+mm)*TT + t)*DECD + k]; }
        __syncthreads();
        float a0=sb[j], a1=sb[32+j], a2=sb[64+j], a3=sb[96+j];
        #pragma unroll
        for (int k=0;k<32;k++){
            float zv = sz[m*33+k], hv = sh[m*33+k];
            a0 += zv*sWi[( j   )*33+k] + hv*sWh[( j   )*33+k];
            a1 += zv*sWi[(32+j)*33+k]  + hv*sWh[(32+j)*33+k];
            a2 += zv*sWi[(64+j)*33+k]  + hv*sWh[(64+j)*33+k];
            a3 += zv*sWi[(96+j)*33+k]  + hv*sWh[(96+j)*33+k];
        }
        float iv=sigmoidf_(a0), fv=sigmoidf_(a1), gv=tanhf(a2), ov=sigmoidf_(a3);
        float cn = fv*sc[m*33+j] + iv*gv;
        float hn = ov*tanhf(cn);
        __syncthreads();
        sh[m*33+j]=hn; sc[m*33+j]=cn;
        g_emb[((size_t)(b0+m)*TBAR + t)*DECD + j] = hn;
        __syncthreads();
    }
}

// ---------------- decoder (exact R6) ----------------
__global__ void __launch_bounds__(256) decoder_kernel(
    const float* __restrict__ x, const float* __restrict__ h0in, const float* __restrict__ c0in,
    const float* __restrict__ Wih, const float* __restrict__ Whh, const float* __restrict__ bias,
    const float* __restrict__ Wlin, const float* __restrict__ blin,
    float* __restrict__ notes)
{
    extern __shared__ float smd[];
    float* sWi = smd;
    float* sWh = sWi + 128*93;
    float* sb  = sWh + 128*33;
    float* sWl = sb + 128;
    float* sbl = sWl + 64*33;
    const int tid = threadIdx.x;
    for (int i=tid; i<128*93; i+=256) sWi[i] = Wih[i];
    for (int i=tid; i<128*32; i+=256){ int cc=i>>5, k=i&31; sWh[cc*33+k] = Whh[i]; }
    if (tid < 128) sb[tid] = bias[tid];
    for (int i=tid; i<64*32; i+=256){ int cc=i>>5, k=i&31; sWl[cc*33+k] = (cc<PP) ? Wlin[i] : 0.f; }
    if (tid < 64) sbl[tid] = (tid<PP) ? blin[tid] : 0.f;
    __syncthreads();

    const int w = tid>>5, lane = tid&31;
    const int row  = blockIdx.x*8 + w;
    const int bidx = row>>4, bar = row&15;
    float h = h0in[((size_t)bar*BB + bidx)*DECD + lane];
    float c = c0in[((size_t)bar*BB + bidx)*DECD + lane];
    const float emb = g_emb[(size_t)row*DECD + lane];
    const unsigned FULL = 0xffffffffu;
    const int c0_=lane, c1_=32+lane, c2_=64+lane, c3_=96+lane;

    for (int n=0;n<16;n++){
        const int time = bar*16 + n;
        float t0 = 0.f, t1 = 0.f;
        if (time > 0){
            const float* xr = x + ((size_t)bidx*TT + time-1)*PP;
            t0 = xr[lane];
            if (lane < 29) t1 = xr[32+lane];
        }
        float a0=sb[c0_], a1=sb[c1_], a2=sb[c2_], a3=sb[c3_];
        #pragma unroll
        for (int k=0;k<32;k++){
            float av = __shfl_sync(FULL, emb, k);
            a0 = fmaf(av, sWi[c0_*93+k], a0); a1 = fmaf(av, sWi[c1_*93+k], a1);
            a2 = fmaf(av, sWi[c2_*93+k], a2); a3 = fmaf(av, sWi[c3_*93+k], a3);
        }
        #pragma unroll
        for (int k=0;k<32;k++){
            float av = __shfl_sync(FULL, t0, k); const int kk=32+k;
            a0 = fmaf(av, sWi[c0_*93+kk], a0); a1 = fmaf(av, sWi[c1_*93+kk], a1);
            a2 = fmaf(av, sWi[c2_*93+kk], a2); a3 = fmaf(av, sWi[c3_*93+kk], a3);
        }
        #pragma unroll
        for (int k=0;k<29;k++){
            float av = __shfl_sync(FULL, t1, k); const int kk=64+k;
            a0 = fmaf(av, sWi[c0_*93+kk], a0); a1 = fmaf(av, sWi[c1_*93+kk], a1);
            a2 = fmaf(av, sWi[c2_*93+kk], a2); a3 = fmaf(av, sWi[c3_*93+kk], a3);
        }
        #pragma unroll
        for (int k=0;k<32;k++){
            float av = __shfl_sync(FULL, h, k);
            a0 = fmaf(av, sWh[c0_*33+k], a0); a1 = fmaf(av, sWh[c1_*33+k], a1);
            a2 = fmaf(av, sWh[c2_*33+k], a2); a3 = fmaf(av, sWh[c3_*33+k], a3);
        }
        float iv=sigmoidf_(a0), fv=sigmoidf_(a1), gv=tanhf(a2), ov=sigmoidf_(a3);
        c = fv*c + iv*gv;
        h = ov*tanhf(c);

        float l0 = sbl[lane], l1 = sbl[32+lane];
        #pragma unroll
        for (int k=0;k<32;k++){
            float hv = __shfl_sync(FULL, h, k);
            l0 = fmaf(hv, sWl[lane*33+k], l0);
            l1 = fmaf(hv, sWl[(32+lane)*33+k], l1);
        }
        float l1m = (lane < 29) ? l1 : -1e30f;
        float mx = fmaxf(l0, l1m);
        #pragma unroll
        for (int off=16; off; off>>=1) mx = fmaxf(mx, __shfl_xor_sync(FULL, mx, off));
        float e0 = __expf(l0 - mx);
        float e1 = (lane < 29) ? __expf(l1 - mx) : 0.f;
        float s = e0 + e1;
        #pragma unroll
        for (int off=16; off; off>>=1) s += __shfl_xor_sync(FULL, s, off);
        const float inv = 1.f/s;
        float* nr = notes + ((size_t)bidx*TT + time)*PP;
        nr[lane] = e0*inv;
        if (lane < 29) nr[32+lane] = e1*inv;
    }
}

// ---------------- launch ----------------
extern "C" void kernel_launch(void* const* d_in, const int* in_sizes, int n_in,
                              void* d_out, int out_size)
{
    const float* x        = (const float*)d_in[0];
    const float* eps      = (const float*)d_in[1];
    const float* dec_h0   = (const float*)d_in[2];
    const float* dec_c0   = (const float*)d_in[3];
    const float* eWih_f   = (const float*)d_in[4];
    const float* eWhh_f   = (const float*)d_in[5];
    const float* eb_f     = (const float*)d_in[6];
    const float* eWih_b   = (const float*)d_in[7];
    const float* eWhh_b   = (const float*)d_in[8];
    const float* eb_b     = (const float*)d_in[9];
    const float* Wout     = (const float*)d_in[10];
    const float* bout     = (const float*)d_in[11];
    const float* Wz       = (const float*)d_in[12];
    const float* bz       = (const float*)d_in[13];
    const float* conWih   = (const float*)d_in[14];
    const float* conWhh   = (const float*)d_in[15];
    const float* conb     = (const float*)d_in[16];
    const float* dWih     = (const float*)d_in[17];
    const float* dWhh     = (const float*)d_in[18];
    const float* db       = (const float*)d_in[19];
    const float* Wlin     = (const float*)d_in[20];
    const float* blin     = (const float*)d_in[21];

    float* out   = (float*)d_out;
    float* notes = out;
    float* zout  = out + (size_t)NROWS*PP;
    float* muo   = zout + (size_t)NROWS*DECD;
    float* lvo   = muo  + (size_t)NROWS*LATD;

    wsplit_kernel<<<256, 1024>>>(eWhh_f, eWhh_b);

    cudaFuncSetAttribute(xproj_kernel, cudaFuncAttributeMaxDynamicSharedMemorySize, 66048);
    xproj_kernel<<<dim3(32, TT, 2), 256, 66048>>>(x, eWih_f, eb_f, eWih_b, eb_b);

    cudaFuncSetAttribute(enc_persist_kernel, cudaFuncAttributeMaxDynamicSharedMemorySize, ENC_SMEM);
    enc_persist_kernel<<<NBLK, 512, ENC_SMEM>>>();

    cudaFuncSetAttribute(encout_fp16_kernel, cudaFuncAttributeMaxDynamicSharedMemorySize, EF_SMEM);
    encout_fp16_kernel<<<dim3(8, NROWS/128), 256, EF_SMEM>>>(Wout, bout, muo, lvo);

    zproj_kernel<<<NROWS/128, 256>>>(muo, lvo, eps, Wz, bz, zout);

    conductor_kernel<<<BB/8, 256>>>(zout, conWih, conWhh, conb);

    cudaFuncSetAttribute(decoder_kernel, cudaFuncAttributeMaxDynamicSharedMemorySize, 73728);
    decoder_kernel<<<(BB*TBAR)/8, 256, 73728>>>(x, dec_h0, dec_c0,
                                                dWih, dWhh, db, Wlin, blin, notes);
}

// round 16
// speedup vs baseline: 1.1628x; 1.0389x over previous
#include <cuda_runtime.h>
#include <cuda_fp16.h>
#include <math.h>
#include <stdint.h>

#define BB   512
#define TT   256
#define PP   61
#define HE   256
#define LATD 512
#define DECD 32
#define TBAR 16
#define NROWS (BB*TT)   // 131072
#define NBLK 128

// ---------------- scratch ----------------
__device__ __half g_enc[(size_t)NROWS*512];         // (B*T, 2H) fp16 (encout uses hi only)
__device__ float g_xp[(size_t)2*TT*1024*BB];        // [dir][pos][n][b]
__device__ float g_h[2*2*BB*HE];                    // [dir][parity][b][j]
__device__ float g_emb[(size_t)BB*TBAR*DECD];
__device__ uint32_t g_whh[270336];                  // [dir][nt][n 128][kp 132] fp16x2 hi
__device__ uint32_t g_whl[270336];                  // fp16x2 lo

__device__ unsigned g_cnt[16];
__device__ volatile unsigned g_sns[16];

typedef unsigned long long u64;

__device__ __forceinline__ float sigmoidf_(float v){ return 1.f/(1.f+__expf(-v)); }
__device__ __forceinline__ float tanh_ap(float v){
    float r; asm("tanh.approx.f32 %0, %1;" : "=f"(r) : "f"(v)); return r;
}
__device__ __forceinline__ u64 pk2(float lo, float hi){
    u64 r; asm("mov.b64 %0, {%1,%2};" : "=l"(r) : "f"(lo), "f"(hi)); return r;
}
__device__ __forceinline__ void upk2(u64 v, float &lo, float &hi){
    asm("mov.b64 {%0,%1}, %2;" : "=f"(lo), "=f"(hi) : "l"(v));
}
__device__ __forceinline__ void ffma2(u64 &d, u64 a, u64 b){
    asm("fma.rn.f32x2 %0, %1, %2, %0;" : "+l"(d) : "l"(a), "l"(b));
}
__device__ __forceinline__ void mma16(float &d0, float &d1, float &d2, float &d3,
    uint32_t a0, uint32_t a1, uint32_t a2, uint32_t a3, uint32_t b0, uint32_t b1){
    asm volatile("mma.sync.aligned.m16n8k16.row.col.f32.f16.f16.f32 "
        "{%0,%1,%2,%3},{%4,%5,%6,%7},{%8,%9},{%0,%1,%2,%3};"
        : "+f"(d0),"+f"(d1),"+f"(d2),"+f"(d3)
        : "r"(a0),"r"(a1),"r"(a2),"r"(a3),"r"(b0),"r"(b1));
}

// ---------------- wsplit (exact R13) ----------------
__global__ void __launch_bounds__(1024) wsplit_kernel(
    const float* __restrict__ Whh_f, const float* __restrict__ Whh_b)
{
    const int u = blockIdx.x*1024 + threadIdx.x;
    const int dir = u >> 17;
    const int rem = u & 131071;
    const int nt  = rem >> 14;
    const int rem2 = rem & 16383;
    const int n = rem2 >> 7, kp = rem2 & 127;
    const int k = kp*2;
    const int wrow = (n>>5)*HE + nt*32 + (n&31);
    const float* W = dir ? Whh_b : Whh_f;
    float v0 = __ldg(W + (size_t)wrow*HE + k);
    float v1 = __ldg(W + (size_t)wrow*HE + k + 1);
    __half2 h2 = __floats2half2_rn(v0, v1);
    __half2 l2 = __floats2half2_rn(v0 - __low2float(h2), v1 - __high2float(h2));
    const int dst = ((dir*8 + nt)*128 + n)*132 + kp;
    g_whh[dst] = *(const uint32_t*)&h2;
    g_whl[dst] = *(const uint32_t*)&l2;
}

// ---------------- xproj (exact R6) ----------------
__global__ void __launch_bounds__(256) xproj_kernel(
    const float* __restrict__ x,
    const float* __restrict__ Wih_f, const float* __restrict__ b_f,
    const float* __restrict__ Wih_b, const float* __restrict__ b_b)
{
    extern __shared__ float sxp[];
    float* sWt = sxp;
    float* sXt = sxp + 61*132;
    const int n0  = (blockIdx.x >> 2)*128;
    const int b0  = (blockIdx.x & 3)*128;
    const int pos = blockIdx.y;
    const int dir = blockIdx.z;
    const float* Wih  = dir ? Wih_b : Wih_f;
    const float* bias = dir ? b_b   : b_f;
    const int tid = threadIdx.x, tx = tid&15, ty = tid>>4;

    {
        const int row = tid >> 1, ks = (tid & 1)*32;
        const float* wsrc = Wih + (size_t)(n0+row)*PP;
        const float* xsrc = x + ((size_t)(b0+row)*TT + pos)*PP;
        #pragma unroll
        for (int i=0;i<32;i++){
            int k = ks + i;
            if (k < PP){
                sWt[k*132 + row] = __ldg(wsrc + k);
                sXt[k*132 + row] = __ldg(xsrc + k);
            }
        }
    }
    __syncthreads();

    u64 acc[8][4];
    #pragma unroll
    for (int r=0;r<8;r++)
        #pragma unroll
        for (int c=0;c<4;c++) acc[r][c] = 0ull;

    for (int k=0;k<PP;k++){
        float4 a0 = *(const float4*)&sWt[k*132 + ty*8];
        float4 a1 = *(const float4*)&sWt[k*132 + ty*8 + 4];
        ulonglong2 b0v = *(const ulonglong2*)&sXt[k*132 + tx*8];
        ulonglong2 b1v = *(const ulonglong2*)&sXt[k*132 + tx*8 + 4];
        u64 bd[4] = { b0v.x, b0v.y, b1v.x, b1v.y };
        u64 ad[8] = { pk2(a0.x,a0.x), pk2(a0.y,a0.y), pk2(a0.z,a0.z), pk2(a0.w,a0.w),
                      pk2(a1.x,a1.x), pk2(a1.y,a1.y), pk2(a1.z,a1.z), pk2(a1.w,a1.w) };
        #pragma unroll
        for (int r=0;r<8;r++)
            #pragma unroll
            for (int c=0;c<4;c++) ffma2(acc[r][c], ad[r], bd[c]);
    }

    #pragma unroll
    for (int r=0;r<8;r++){
        const int n = n0 + ty*8 + r;
        const float bv = __ldg(bias + n);
        float* orow = g_xp + (((size_t)dir*TT + pos)*1024 + n)*BB + b0 + tx*8;
        float4 w0, w1;
        upk2(acc[r][0], w0.x, w0.y); upk2(acc[r][1], w0.z, w0.w);
        upk2(acc[r][2], w1.x, w1.y); upk2(acc[r][3], w1.z, w1.w);
        w0.x+=bv; w0.y+=bv; w0.z+=bv; w0.w+=bv;
        w1.x+=bv; w1.y+=bv; w1.z+=bv; w1.w+=bv;
        *(float4*)orow = w0;
        *(float4*)(orow+4) = w1;
    }
}

// ---------------- persistent encoder: fp16 2-pass mma, 512 threads (exact R15 + fp16 g_enc) ----------------
#define SW_H 0
#define SW_L 16896
#define SA_H 33792
#define ENC_SMEM ((33792 + 8448)*4)   // 168960 bytes

__global__ void __launch_bounds__(512, 1) enc_persist_kernel()
{
    extern __shared__ uint32_t smu[];
    __shared__ unsigned s_sense;

    const int bid = blockIdx.x;
    const int dir = bid >> 6;
    const int bt  = (bid >> 3) & 7;
    const int nt  = bid & 7;
    const int b0 = bt*64, j0 = nt*32;
    const int grp = bid >> 3;

    const int tid = threadIdx.x;
    if (tid == 0) s_sense = g_sns[grp];

    {
        const uint32_t* whsrc = g_whh + (size_t)(dir*8 + nt)*16896;
        const uint32_t* wlsrc = g_whl + (size_t)(dir*8 + nt)*16896;
        for (int u = tid; u < 16896; u += 512){
            smu[SW_H + u] = whsrc[u];
            smu[SW_L + u] = wlsrc[u];
        }
    }
    for (int i = tid; i < 64*32; i += 512){
        const int r = i >> 5, j = j0 + (i & 31);
        g_h[((dir*2+0)*BB + b0 + r)*HE + j] = 0.f;
    }

#define GRID_BAR() do {                                            \
        __threadfence();                                           \
        __syncthreads();                                           \
        if (tid == 0){                                             \
            unsigned my = s_sense;                                 \
            unsigned old = atomicAdd(&g_cnt[grp], 1u);             \
            if (old == 7u){                                        \
                g_cnt[grp] = 0;                                    \
                __threadfence();                                   \
                g_sns[grp] = my ^ 1u;                              \
            } else {                                               \
                while (g_sns[grp] == my) __nanosleep(32);          \
            }                                                      \
            s_sense = my ^ 1u;                                     \
        }                                                          \
        __syncthreads();                                           \
    } while(0)

    GRID_BAR();

    const int lane = tid & 31, wid = tid >> 5;
    const int wm = wid & 1, wn = wid >> 1;
    const int g = lane >> 2, t4 = lane & 3;
    const int tx = tid & 31;
    const int ty = tid >> 5;
    const int jj = j0 + tx;

    const int s_row = tid >> 3, s_q = tid & 7;

    float creg[4] = {0.f, 0.f, 0.f, 0.f};

    for (int t=0; t<TT; t++){
        const int tpos = dir ? (TT-1-t) : t;
        const int par = t & 1, parn = par ^ 1;
        const float* hr = g_h + ((size_t)(dir*2+par)*BB + b0 + s_row)*HE;

        #pragma unroll
        for (int i=0;i<8;i++){
            const int j = s_q*4 + i*32;
            float4 v = __ldcg((const float4*)(hr + j));
            __half2 h0 = __floats2half2_rn(v.x, v.y);
            __half2 h1 = __floats2half2_rn(v.z, v.w);
            uint2 hw = make_uint2(*(const uint32_t*)&h0, *(const uint32_t*)&h1);
            *(uint2*)&smu[SA_H + s_row*132 + (j>>1)] = hw;
        }
        __syncthreads();

        float acc[2][2][4];
        #pragma unroll
        for (int a=0;a<2;a++)
            #pragma unroll
            for (int b=0;b<2;b++)
                #pragma unroll
                for (int c=0;c<4;c++) acc[a][b][c] = 0.f;

        #pragma unroll
        for (int kg=0; kg<16; kg++){
            const int base = kg*8;
            uint32_t ah[2][4];
            #pragma unroll
            for (int mt=0;mt<2;mt++){
                const int r = wm*32 + mt*16 + g;
                ah[mt][0] = smu[SA_H + r    *132 + base + t4];
                ah[mt][1] = smu[SA_H + (r+8)*132 + base + t4];
                ah[mt][2] = smu[SA_H + r    *132 + base + 4 + t4];
                ah[mt][3] = smu[SA_H + (r+8)*132 + base + 4 + t4];
            }
            #pragma unroll
            for (int ntI=0;ntI<2;ntI++){
                const int n = wn*16 + ntI*8 + g;
                uint32_t bh0 = smu[SW_H + n*132 + base + t4];
                uint32_t bh1 = smu[SW_H + n*132 + base + 4 + t4];
                uint32_t bl0 = smu[SW_L + n*132 + base + t4];
                uint32_t bl1 = smu[SW_L + n*132 + base + 4 + t4];
                #pragma unroll
                for (int mt=0;mt<2;mt++){
                    mma16(acc[mt][ntI][0],acc[mt][ntI][1],acc[mt][ntI][2],acc[mt][ntI][3],
                          ah[mt][0],ah[mt][1],ah[mt][2],ah[mt][3], bh0,bh1);
                    mma16(acc[mt][ntI][0],acc[mt][ntI][1],acc[mt][ntI][2],acc[mt][ntI][3],
                          ah[mt][0],ah[mt][1],ah[mt][2],ah[mt][3], bl0,bl1);
                }
            }
        }
        __syncthreads();

        float* Cb = (float*)&smu[SA_H];
        #pragma unroll
        for (int mt=0;mt<2;mt++){
            const int r = wm*32 + mt*16 + g;
            #pragma unroll
            for (int ntI=0;ntI<2;ntI++){
                const int col = wn*16 + ntI*8 + t4*2;
                *(float2*)&Cb[r    *132 + col] = make_float2(acc[mt][ntI][0], acc[mt][ntI][1]);
                *(float2*)&Cb[(r+8)*132 + col] = make_float2(acc[mt][ntI][2], acc[mt][ntI][3]);
            }
        }
        __syncthreads();

        const float* xpb = g_xp + ((size_t)dir*TT + tpos)*1024*BB;
        float4 xg[4];
        #pragma unroll
        for (int g2=0; g2<4; g2++)
            xg[g2] = __ldg((const float4*)(xpb + (size_t)(g2*HE + jj)*BB + b0 + ty*4));
        #pragma unroll
        for (int p=0;p<4;p++){
            const int r = ty*4 + p;
            float pi = Cb[r*132 +      tx] + ((const float*)&xg[0])[p];
            float pf = Cb[r*132 + 32 + tx] + ((const float*)&xg[1])[p];
            float pg = Cb[r*132 + 64 + tx] + ((const float*)&xg[2])[p];
            float po = Cb[r*132 + 96 + tx] + ((const float*)&xg[3])[p];
            float iv = sigmoidf_(pi);
            float fv = sigmoidf_(pf);
            float gv = tanh_ap  (pg);
            float ov = sigmoidf_(po);
            float cn = fv*creg[p] + iv*gv;
            creg[p] = cn;
            float hn = ov*tanh_ap(cn);
            const int gb = b0 + r;
            g_enc[((size_t)gb*TT + tpos)*512 + dir*HE + jj] = __float2half_rn(hn);
            g_h[((size_t)(dir*2+parn)*BB + gb)*HE + jj] = hn;
        }

        if (t+1 < TT) GRID_BAR();
    }
#undef GRID_BAR
}

// ---------------- encoderOut: fp16 2-pass mma; A read direct from fp16 g_enc ----------------
#define EF_PAD  20
#define EF_MAT  (128*EF_PAD)
#define EF_STG  (3*EF_MAT)
#define EF_SMEM (2*EF_STG*4)

__global__ void __launch_bounds__(256,1) encout_fp16_kernel(
    const float* __restrict__ Wout, const float* __restrict__ bout,
    float* __restrict__ mu_out, float* __restrict__ lv_out)
{
    extern __shared__ uint32_t smo[];
    const int tid = threadIdx.x, lane = tid & 31, wid = tid >> 5;
    const int wm = wid & 3, wn = wid >> 2;
    const int n0 = blockIdx.x*128, r0 = blockIdx.y*128;
    const int g = lane >> 2, t4 = lane & 3;

    float acc[2][8][4];
    #pragma unroll
    for (int a=0;a<2;a++)
        #pragma unroll
        for (int b=0;b<8;b++)
            #pragma unroll
            for (int c=0;c<4;c++) acc[a][b][c] = 0.f;

    const int srow  = tid >> 1;
    const int shalf = tid & 1;
    // A source: fp16 g_enc, 16 halves (= 8 u32 k-pairs) per thread per chunk
    const uint32_t* asrc = (const uint32_t*)(g_enc + (size_t)(r0+srow)*512 + shalf*16);
    const float*    bsrc = Wout + (size_t)(n0+srow)*512 + shalf*16;
    const int sdst = srow*EF_PAD + shalf*8;

    auto sts_hilo = [&](uint32_t* hi_base, uint32_t* lo_base, const float4* v){
        #pragma unroll
        for (int q=0;q<4;q++){
            __half2 h0 = __floats2half2_rn(v[q].x, v[q].y);
            __half2 h1 = __floats2half2_rn(v[q].z, v[q].w);
            __half2 l0 = __floats2half2_rn(v[q].x - __low2float(h0), v[q].y - __high2float(h0));
            __half2 l1 = __floats2half2_rn(v[q].z - __low2float(h1), v[q].w - __high2float(h1));
            *(__half2*)&hi_base[sdst + q*2]     = h0;
            *(__half2*)&hi_base[sdst + q*2 + 1] = h1;
            *(__half2*)&lo_base[sdst + q*2]     = l0;
            *(__half2*)&lo_base[sdst + q*2 + 1] = l1;
        }
    };
    auto sts_a = [&](uint32_t* hi_base, uint4 a0, uint4 a1){
        *(uint4*)&hi_base[sdst]     = a0;
        *(uint4*)&hi_base[sdst + 4] = a1;
    };

    uint4 aw0, aw1;
    float4 bv[4];
    aw0 = __ldg((const uint4*)asrc);
    aw1 = __ldg(((const uint4*)asrc) + 1);
    #pragma unroll
    for (int j=0;j<4;j++) bv[j] = __ldg((const float4*)(bsrc + j*4));
    sts_a(smo, aw0, aw1);
    sts_hilo(smo + EF_MAT, smo + 2*EF_MAT, bv);
    __syncthreads();

    for (int c=0;c<16;c++){
        if (c+1 < 16){
            aw0 = __ldg((const uint4*)(asrc + (c+1)*16));
            aw1 = __ldg((const uint4*)(asrc + (c+1)*16) + 1);
            #pragma unroll
            for (int j=0;j<4;j++)
                bv[j] = __ldg((const float4*)(bsrc + (c+1)*32 + j*4));
        }
        const uint32_t* AH = smo + (c&1)*EF_STG;
        const uint32_t* BH = AH + EF_MAT;
        const uint32_t* BL = AH + 2*EF_MAT;

        #pragma unroll
        for (int ks=0; ks<2; ks++){
            const int base = ks*8;
            uint32_t ah[2][4];
            #pragma unroll
            for (int mt=0;mt<2;mt++){
                const int r = wm*32 + mt*16 + g;
                ah[mt][0] = AH[ r    *EF_PAD + base + t4];
                ah[mt][1] = AH[(r+8) *EF_PAD + base + t4];
                ah[mt][2] = AH[ r    *EF_PAD + base + 4 + t4];
                ah[mt][3] = AH[(r+8) *EF_PAD + base + 4 + t4];
            }
            #pragma unroll
            for (int ntI=0;ntI<8;ntI++){
                const int n = wn*64 + ntI*8 + g;
                uint32_t bh0 = BH[n*EF_PAD + base + t4];
                uint32_t bh1 = BH[n*EF_PAD + base + 4 + t4];
                uint32_t bl0 = BL[n*EF_PAD + base + t4];
                uint32_t bl1 = BL[n*EF_PAD + base + 4 + t4];
                #pragma unroll
                for (int mt=0;mt<2;mt++){
                    mma16(acc[mt][ntI][0],acc[mt][ntI][1],acc[mt][ntI][2],acc[mt][ntI][3],
                          ah[mt][0],ah[mt][1],ah[mt][2],ah[mt][3], bh0,bh1);
                    mma16(acc[mt][ntI][0],acc[mt][ntI][1],acc[mt][ntI][2],acc[mt][ntI][3],
                          ah[mt][0],ah[mt][1],ah[mt][2],ah[mt][3], bl0,bl1);
                }
            }
        }
        if (c+1 < 16){
            uint32_t* NB = smo + ((c+1)&1)*EF_STG;
            sts_a(NB, aw0, aw1);
            sts_hilo(NB + EF_MAT, NB + 2*EF_MAT, bv);
        }
        __syncthreads();
    }

    #pragma unroll
    for (int mt=0;mt<2;mt++){
        const size_t row = (size_t)r0 + wm*32 + mt*16 + g;
        #pragma unroll
        for (int ntI=0;ntI<8;ntI++){
            const int col = n0 + wn*64 + ntI*8 + t4*2;
            const float bb0 = __ldg(bout + col), bb1 = __ldg(bout + col + 1);
            float v0 = acc[mt][ntI][0] + bb0, v1 = acc[mt][ntI][1] + bb1;
            float v2 = acc[mt][ntI][2] + bb0, v3 = acc[mt][ntI][3] + bb1;
            if (n0 < LATD){
                *(float2*)(mu_out + row*LATD + col)     = make_float2(v0, v1);
                *(float2*)(mu_out + (row+8)*LATD + col) = make_float2(v2, v3);
            } else {
                v0 = (v0>20.f)?v0:log1pf(__expf(v0));
                v1 = (v1>20.f)?v1:log1pf(__expf(v1));
                v2 = (v2>20.f)?v2:log1pf(__expf(v2));
                v3 = (v3>20.f)?v3:log1pf(__expf(v3));
                *(float2*)(lv_out + row*LATD + (col-LATD))     = make_float2(v0, v1);
                *(float2*)(lv_out + (row+8)*LATD + (col-LATD)) = make_float2(v2, v3);
            }
        }
    }
}

// ---------------- z projection (exact R6) ----------------
__global__ void __launch_bounds__(256) zproj_kernel(
    const float* __restrict__ mu, const float* __restrict__ lv, const float* __restrict__ eps,
    const float* __restrict__ Wz, const float* __restrict__ bz, float* __restrict__ zout)
{
    const int r0 = blockIdx.x*128;
    __shared__ float sA[8*132], sB[8*33];
    const int tid = threadIdx.x, tx = tid&15, ty = tid>>4;
    const int m = tid>>1, kb = (tid&1)*4;
    const size_t rr = (size_t)r0 + m;
    const int bidx = (int)(rr >> 8);
    const float* murow  = mu  + rr*LATD;
    const float* lvrow  = lv  + rr*LATD;
    const float* epsrow = eps + (size_t)bidx*LATD;
    const int bnn = tid>>3, bkk = tid&7;

    float acc[8][2] = {};
    float ra[4], rb;
    auto fetch = [&](int k0){
        float4 m4 = *(const float4*)&murow[k0+kb];
        float4 l4 = *(const float4*)&lvrow[k0+kb];
        float4 e4 = *(const float4*)&epsrow[k0+kb];
        ra[0] = m4.x + e4.x*__expf(2.f*l4.x);
        ra[1] = m4.y + e4.y*__expf(2.f*l4.y);
        ra[2] = m4.z + e4.z*__expf(2.f*l4.z);
        ra[3] = m4.w + e4.w*__expf(2.f*l4.w);
        rb = Wz[(size_t)bnn*LATD + k0 + bkk];
    };
    fetch(0);
    for (int ch=0; ch<64; ch++){
        __syncthreads();
        #pragma unroll
        for (int i=0;i<4;i++) sA[(kb+i)*132+m] = ra[i];
        sB[bkk*33 + bnn] = rb;
        __syncthreads();
        if (ch<63) fetch((ch+1)*8);
        #pragma unroll
        for (int kk=0;kk<8;kk++){
            float4 a0 = *(const float4*)&sA[kk*132 + ty*8];
            float4 a1 = *(const float4*)&sA[kk*132 + ty*8 + 4];
            float a[8] = {a0.x,a0.y,a0.z,a0.w,a1.x,a1.y,a1.z,a1.w};
            float bv0 = sB[kk*33 + tx*2 + 0];
            float bv1 = sB[kk*33 + tx*2 + 1];
            #pragma unroll
            for (int r=0;r<8;r++){
                acc[r][0] = fmaf(a[r], bv0, acc[r][0]);
                acc[r][1] = fmaf(a[r], bv1, acc[r][1]);
            }
        }
    }
    #pragma unroll
    for (int ri=0;ri<8;ri++){
        const size_t r = r0 + ty*8 + ri;
        #pragma unroll
        for (int ci=0;ci<2;ci++){
            const int col = tx*2 + ci;
            zout[r*DECD + col] = acc[ri][ci] + bz[col];
        }
    }
}

// ---------------- conductor LSTM (exact R6) ----------------
__global__ void __launch_bounds__(256) conductor_kernel(
    const float* __restrict__ zout, const float* __restrict__ Wih,
    const float* __restrict__ Whh, const float* __restrict__ bias)
{
    __shared__ float sWi[128*33], sWh[128*33], sb[128];
    __shared__ float sh[8*33], sc[8*33], sz[8*33];
    const int tid = threadIdx.x;
    const int b0 = blockIdx.x*8;
    for (int i=tid; i<128*32; i+=256){ int cc=i>>5, k=i&31; sWi[cc*33+k]=Wih[i]; sWh[cc*33+k]=Whh[i]; }
    if (tid < 128) sb[tid] = bias[tid];
    { int mm=tid>>5, k=tid&31; sh[mm*33+k]=0.f; sc[mm*33+k]=0.f; }
    __syncthreads();

    const int j  = tid & 31;
    const int m  = tid >> 5;
    for (int t=0; t<TBAR; t++){
        { int mm=tid>>5, k=tid&31;
          sz[mm*33+k] = zout[((size_t)(b0+mm)*TT + t)*DECD + k]; }
        __syncthreads();
        float a0=sb[j], a1=sb[32+j], a2=sb[64+j], a3=sb[96+j];
        #pragma unroll
        for (int k=0;k<32;k++){
            float zv = sz[m*33+k], hv = sh[m*33+k];
            a0 += zv*sWi[( j   )*33+k] + hv*sWh[( j   )*33+k];
            a1 += zv*sWi[(32+j)*33+k]  + hv*sWh[(32+j)*33+k];
            a2 += zv*sWi[(64+j)*33+k]  + hv*sWh[(64+j)*33+k];
            a3 += zv*sWi[(96+j)*33+k]  + hv*sWh[(96+j)*33+k];
        }
        float iv=sigmoidf_(a0), fv=sigmoidf_(a1), gv=tanhf(a2), ov=sigmoidf_(a3);
        float cn = fv*sc[m*33+j] + iv*gv;
        float hn = ov*tanhf(cn);
        __syncthreads();
        sh[m*33+j]=hn; sc[m*33+j]=cn;
        g_emb[((size_t)(b0+m)*TBAR + t)*DECD + j] = hn;
        __syncthreads();
    }
}

// ---------------- decoder (exact R6) ----------------
__global__ void __launch_bounds__(256) decoder_kernel(
    const float* __restrict__ x, const float* __restrict__ h0in, const float* __restrict__ c0in,
    const float* __restrict__ Wih, const float* __restrict__ Whh, const float* __restrict__ bias,
    const float* __restrict__ Wlin, const float* __restrict__ blin,
    float* __restrict__ notes)
{
    extern __shared__ float smd[];
    float* sWi = smd;
    float* sWh = sWi + 128*93;
    float* sb  = sWh + 128*33;
    float* sWl = sb + 128;
    float* sbl = sWl + 64*33;
    const int tid = threadIdx.x;
    for (int i=tid; i<128*93; i+=256) sWi[i] = Wih[i];
    for (int i=tid; i<128*32; i+=256){ int cc=i>>5, k=i&31; sWh[cc*33+k] = Whh[i]; }
    if (tid < 128) sb[tid] = bias[tid];
    for (int i=tid; i<64*32; i+=256){ int cc=i>>5, k=i&31; sWl[cc*33+k] = (cc<PP) ? Wlin[i] : 0.f; }
    if (tid < 64) sbl[tid] = (tid<PP) ? blin[tid] : 0.f;
    __syncthreads();

    const int w = tid>>5, lane = tid&31;
    const int row  = blockIdx.x*8 + w;
    const int bidx = row>>4, bar = row&15;
    float h = h0in[((size_t)bar*BB + bidx)*DECD + lane];
    float c = c0in[((size_t)bar*BB + bidx)*DECD + lane];
    const float emb = g_emb[(size_t)row*DECD + lane];
    const unsigned FULL = 0xffffffffu;
    const int c0_=lane, c1_=32+lane, c2_=64+lane, c3_=96+lane;

    for (int n=0;n<16;n++){
        const int time = bar*16 + n;
        float t0 = 0.f, t1 = 0.f;
        if (time > 0){
            const float* xr = x + ((size_t)bidx*TT + time-1)*PP;
            t0 = xr[lane];
            if (lane < 29) t1 = xr[32+lane];
        }
        float a0=sb[c0_], a1=sb[c1_], a2=sb[c2_], a3=sb[c3_];
        #pragma unroll
        for (int k=0;k<32;k++){
            float av = __shfl_sync(FULL, emb, k);
            a0 = fmaf(av, sWi[c0_*93+k], a0); a1 = fmaf(av, sWi[c1_*93+k], a1);
            a2 = fmaf(av, sWi[c2_*93+k], a2); a3 = fmaf(av, sWi[c3_*93+k], a3);
        }
        #pragma unroll
        for (int k=0;k<32;k++){
            float av = __shfl_sync(FULL, t0, k); const int kk=32+k;
            a0 = fmaf(av, sWi[c0_*93+kk], a0); a1 = fmaf(av, sWi[c1_*93+kk], a1);
            a2 = fmaf(av, sWi[c2_*93+kk], a2); a3 = fmaf(av, sWi[c3_*93+kk], a3);
        }
        #pragma unroll
        for (int k=0;k<29;k++){
            float av = __shfl_sync(FULL, t1, k); const int kk=64+k;
            a0 = fmaf(av, sWi[c0_*93+kk], a0); a1 = fmaf(av, sWi[c1_*93+kk], a1);
            a2 = fmaf(av, sWi[c2_*93+kk], a2); a3 = fmaf(av, sWi[c3_*93+kk], a3);
        }
        #pragma unroll
        for (int k=0;k<32;k++){
            float av = __shfl_sync(FULL, h, k);
            a0 = fmaf(av, sWh[c0_*33+k], a0); a1 = fmaf(av, sWh[c1_*33+k], a1);
            a2 = fmaf(av, sWh[c2_*33+k], a2); a3 = fmaf(av, sWh[c3_*33+k], a3);
        }
        float iv=sigmoidf_(a0), fv=sigmoidf_(a1), gv=tanhf(a2), ov=sigmoidf_(a3);
        c = fv*c + iv*gv;
        h = ov*tanhf(c);

        float l0 = sbl[lane], l1 = sbl[32+lane];
        #pragma unroll
        for (int k=0;k<32;k++){
            float hv = __shfl_sync(FULL, h, k);
            l0 = fmaf(hv, sWl[lane*33+k], l0);
            l1 = fmaf(hv, sWl[(32+lane)*33+k], l1);
        }
        float l1m = (lane < 29) ? l1 : -1e30f;
        float mx = fmaxf(l0, l1m);
        #pragma unroll
        for (int off=16; off; off>>=1) mx = fmaxf(mx, __shfl_xor_sync(FULL, mx, off));
        float e0 = __expf(l0 - mx);
        float e1 = (lane < 29) ? __expf(l1 - mx) : 0.f;
        float s = e0 + e1;
        #pragma unroll
        for (int off=16; off; off>>=1) s += __shfl_xor_sync(FULL, s, off);
        const float inv = 1.f/s;
        float* nr = notes + ((size_t)bidx*TT + time)*PP;
        nr[lane] = e0*inv;
        if (lane < 29) nr[32+lane] = e1*inv;
    }
}

// ---------------- launch ----------------
extern "C" void kernel_launch(void* const* d_in, const int* in_sizes, int n_in,
                              void* d_out, int out_size)
{
    const float* x        = (const float*)d_in[0];
    const float* eps      = (const float*)d_in[1];
    const float* dec_h0   = (const float*)d_in[2];
    const float* dec_c0   = (const float*)d_in[3];
    const float* eWih_f   = (const float*)d_in[4];
    const float* eWhh_f   = (const float*)d_in[5];
    const float* eb_f     = (const float*)d_in[6];
    const float* eWih_b   = (const float*)d_in[7];
    const float* eWhh_b   = (const float*)d_in[8];
    const float* eb_b     = (const float*)d_in[9];
    const float* Wout     = (const float*)d_in[10];
    const float* bout     = (const float*)d_in[11];
    const float* Wz       = (const float*)d_in[12];
    const float* bz       = (const float*)d_in[13];
    const float* conWih   = (const float*)d_in[14];
    const float* conWhh   = (const float*)d_in[15];
    const float* conb     = (const float*)d_in[16];
    const float* dWih     = (const float*)d_in[17];
    const float* dWhh     = (const float*)d_in[18];
    const float* db       = (const float*)d_in[19];
    const float* Wlin     = (const float*)d_in[20];
    const float* blin     = (const float*)d_in[21];

    float* out   = (float*)d_out;
    float* notes = out;
    float* zout  = out + (size_t)NROWS*PP;
    float* muo   = zout + (size_t)NROWS*DECD;
    float* lvo   = muo  + (size_t)NROWS*LATD;

    wsplit_kernel<<<256, 1024>>>(eWhh_f, eWhh_b);

    cudaFuncSetAttribute(xproj_kernel, cudaFuncAttributeMaxDynamicSharedMemorySize, 66048);
    xproj_kernel<<<dim3(32, TT, 2), 256, 66048>>>(x, eWih_f, eb_f, eWih_b, eb_b);

    cudaFuncSetAttribute(enc_persist_kernel, cudaFuncAttributeMaxDynamicSharedMemorySize, ENC_SMEM);
    enc_persist_kernel<<<NBLK, 512, ENC_SMEM>>>();

    cudaFuncSetAttribute(encout_fp16_kernel, cudaFuncAttributeMaxDynamicSharedMemorySize, EF_SMEM);
    encout_fp16_kernel<<<dim3(8, NROWS/128), 256, EF_SMEM>>>(Wout, bout, muo, lvo);

    zproj_kernel<<<NROWS/128, 256>>>(muo, lvo, eps, Wz, bz, zout);

    conductor_kernel<<<BB/8, 256>>>(zout, conWih, conWhh, conb);

    cudaFuncSetAttribute(decoder_kernel, cudaFuncAttributeMaxDynamicSharedMemorySize, 73728);
    decoder_kernel<<<(BB*TBAR)/8, 256, 73728>>>(x, dec_h0, dec_c0,
                                                dWih, dWhh, db, Wlin, blin, notes);
}